// round 17
// baseline (speedup 1.0000x reference)
#include <cuda_runtime.h>
#include <cuda_pipeline.h>

#define NB       4096        // batch (selection axis)
#define NT       256         // T
#define ND       64          // D
#define NCOL     (NT * ND)   // 16384 columns per tensor
#define KRANK    204         // int(0.05 * 4096), 0-based rank
#define G        16          // columns per block (4 float4 columns = 64 B/row)
#define CAPC     416         // candidate capacity per column (mean 301, sd 16.7)
#define NTHREADS 256
#define NWARP    8
#define NBLOCKS  (2 * NT * (ND / G))   // 2048
#define DEPTH    3           // cp.async pipeline depth (stages in flight)

__device__ float    g_var[2 * NCOL];
__device__ double   g_pa[16];
__device__ double   g_pr[16];
__device__ unsigned g_done2 = 0;

static __device__ __forceinline__ unsigned key_of(float f) {
    unsigned u = __float_as_uint(f);
    unsigned mask = (unsigned)((int)u >> 31) | 0x80000000u;
    return u ^ mask;  // monotone: key order == float ascending order
}
static __device__ __forceinline__ float float_of(unsigned k) {
    unsigned mask = (k & 0x80000000u) ? 0x80000000u : 0xFFFFFFFFu;
    return __uint_as_float(k ^ mask);
}

// find the 256-bin bucket containing 0-based rank k; k becomes rank-in-bucket.
// cc[i] = count of bin (lane*8 + i). Warp-collective.
static __device__ __forceinline__ unsigned find_bucket(const unsigned cc[8], int& kk, int lane) {
    unsigned lanesum = 0;
    #pragma unroll
    for (int i = 0; i < 8; i++) lanesum += cc[i];
    unsigned s = lanesum;
    #pragma unroll
    for (int off = 1; off < 32; off <<= 1) {
        unsigned n = __shfl_up_sync(0xffffffffu, s, off);
        if (lane >= off) s += n;
    }
    unsigned run = s - lanesum;  // exclusive prefix over lanes
    int bucket = -1, nk = 0;
    #pragma unroll
    for (int i = 0; i < 8; i++) {
        if (bucket < 0 && (unsigned)kk >= run && (unsigned)kk < run + cc[i]) {
            bucket = lane * 8 + i;
            nk = kk - (int)run;
        }
        run += cc[i];
    }
    unsigned bal = __ballot_sync(0xffffffffu, bucket >= 0);
    int srcl = __ffs(bal) - 1;
    int bb = __shfl_sync(0xffffffffu, bucket, srcl);
    kk = __shfl_sync(0xffffffffu, nk, srcl);
    return (unsigned)bb;
}

__global__ void __launch_bounds__(NTHREADS, 5)
select_kernel(const float* __restrict__ xf, const float* __restrict__ xr) {
    extern __shared__ unsigned smem[];
    float4*         stg  = (float4*)smem;                     // [DEPTH][256] staging
    unsigned*       seg  = smem + DEPTH * 256 * 4;            // [G][CAPC]
    unsigned*       scnt = seg + G * CAPC;                    // [G]
    unsigned short* hist = (unsigned short*)(scnt + G);       // [NWARP][256] u16

    const int tid  = threadIdx.x;
    const int lane = tid & 31;
    const int w    = tid >> 5;

    const int bid    = blockIdx.x;               // 2048 blocks
    const int tensor = bid >> 10;
    const int rem    = bid & 1023;
    const int t      = rem >> 2;
    const int dgrp   = rem & 3;                  // which group of 16 columns

    const float* src = tensor ? xr : xf;
    const int c = tid & 3;                       // this thread's float4-column (0..3)
    const float4* p = reinterpret_cast<const float4*>(src) + (t * 16 + dgrp * 4 + c)
                      + (size_t)(tid >> 2) * (NCOL / 4);
    const float THR = -1.45f;

    if (tid < G) scnt[tid] = 0;
    __syncthreads();

    // hoisted per-jj column pointers (col = c*4+jj)
    unsigned* cntp[4];
    unsigned* segp[4];
    #pragma unroll
    for (int jj = 0; jj < 4; jj++) {
        cntp[jj] = &scnt[c * 4 + jj];
        segp[jj] = &seg[(c * 4 + jj) * CAPC];
    }

    // ---- cp.async-staged streaming + frozen sparse atomic capture ----
    // Each thread cp.asyncs its OWN 16B per stage and consumes its own bytes:
    // no block sync in the pipeline, no register-held loads, no per-warp DRAM
    // latency ownership. 64 stages of 64 rows; depth-3 double... triple buffer.
    // One commit per iteration (empty in tail) keeps wait_prior's group count
    // constant so wait_prior(DEPTH-1) always frees exactly the consumed stage.
    #pragma unroll
    for (int s = 0; s < DEPTH; s++) {
        __pipeline_memcpy_async(&stg[s * 256 + tid],
                                p + (size_t)(s * 64) * (NCOL / 4), 16);
        __pipeline_commit();
    }

    #pragma unroll 1
    for (int it = 0; it < 64; it++) {
        __pipeline_wait_prior(DEPTH - 1);        // stage `it` is resident
        float4 q = stg[(it % DEPTH) * 256 + tid];
        float vv[4] = {q.x, q.y, q.z, q.w};
        #pragma unroll
        for (int jj = 0; jj < 4; jj++) {
            float v = vv[jj];
            if (v < THR) {
                unsigned slot = atomicAdd(cntp[jj], 1u);
                if (slot < CAPC) segp[jj][slot] = ~__float_as_uint(v);
            }
        }
        if (it + DEPTH < 64)
            __pipeline_memcpy_async(&stg[((it + DEPTH) % DEPTH) * 256 + tid],
                                    p + (size_t)((it + DEPTH) * 64) * (NCOL / 4), 16);
        __pipeline_commit();                     // always: constant group count
    }
    __syncthreads();

    // ---- select: warp w owns columns w and w+8, flat candidate arrays ----
    unsigned short* h   = hist + w * 256;
    unsigned*       h32 = (unsigned*)h;          // for zeroing (128 words)
    const unsigned  lmlt = (1u << lane) - 1u;

    for (int cc2 = 0; cc2 < 2; cc2++) {
        const int col = w + cc2 * NWARP;
        unsigned* colb = seg + col * CAPC;
        const int cnt0 = (int)scnt[col];

        unsigned prefix = 0;
        int k = KRANK;

        if (cnt0 > KRANK && cnt0 <= CAPC) {
            int cntf = cnt0;
            for (int shift = 24; shift >= 0; shift -= 8) {
                #pragma unroll
                for (int i = 0; i < 4; i++) h32[i * 32 + lane] = 0;
                __syncwarp();
                for (int i0 = 0; i0 < cntf; i0 += 32) {
                    int i = i0 + lane;
                    bool a = i < cntf;
                    unsigned key = a ? colb[i] : 0u;
                    unsigned m = __ballot_sync(0xffffffffu, a);
                    if (a) {
                        unsigned bin = (key >> shift) & 255u;
                        unsigned peers = __match_any_sync(m, bin);
                        if (lane == __ffs(peers) - 1)
                            h[bin] = (unsigned short)(h[bin] + __popc(peers));
                    }
                }
                __syncwarp();
                unsigned c8[8];
                #pragma unroll
                for (int i = 0; i < 8; i++) c8[i] = h[lane * 8 + i];
                unsigned bucket = find_bucket(c8, k, lane);
                prefix |= bucket << shift;
                if (shift > 0) {
                    // in-place compaction; writes never pass the read frontier
                    int np = 0;
                    for (int i0 = 0; i0 < cntf; i0 += 32) {
                        int i = i0 + lane;
                        bool a = i < cntf;
                        unsigned key = a ? colb[i] : 0u;
                        bool ok = a && (((key >> shift) & 255u) == bucket);
                        unsigned m = __ballot_sync(0xffffffffu, ok);
                        if (ok) colb[np + __popc(m & lmlt)] = key;
                        np += __popc(m);
                    }
                    cntf = np;
                }
            }
        } else {
            // exact fallback (astronomically rare): 4-pass radix re-reading global
            const int cglob = t * 64 + dgrp * 16 + col;
            for (int shift = 24; shift >= 0; shift -= 8) {
                #pragma unroll
                for (int i = 0; i < 4; i++) h32[i * 32 + lane] = 0;
                __syncwarp();
                for (int i = lane; i < NB; i += 32) {
                    unsigned key = key_of(__ldg(src + (size_t)i * NCOL + cglob));
                    bool act = (shift == 24) ||
                               ((key >> (shift + 8)) == (prefix >> (shift + 8)));
                    unsigned m = __ballot_sync(0xffffffffu, act);
                    if (act) {
                        unsigned bin = (key >> shift) & 255u;
                        unsigned peers = __match_any_sync(m, bin);
                        if (lane == __ffs(peers) - 1)
                            h[bin] = (unsigned short)(h[bin] + __popc(peers));
                    }
                }
                __syncwarp();
                unsigned c8[8];
                #pragma unroll
                for (int i = 0; i < 8; i++) c8[i] = h[lane * 8 + i];
                unsigned bucket = find_bucket(c8, k, lane);
                prefix |= bucket << shift;
            }
        }

        if (lane == 0)
            g_var[tensor * NCOL + t * ND + dgrp * G + col] = float_of(prefix);
    }

    // PDL trigger (neutral but free; helps if select shortens)
    __syncthreads();
    if (tid == 0) cudaTriggerProgrammaticLaunchCompletion();
}

// 16 blocks x 1024 threads, PDL-launched; grid-sync gives g_var visibility.
__global__ void reduce_kernel(float* __restrict__ out) {
    cudaGridDependencySynchronize();

    const int tid  = threadIdx.x;
    const int lane = tid & 31;
    const int wid  = tid >> 5;
    const int i    = blockIdx.x * 1024 + tid;

    float vf = g_var[i];
    float vr = g_var[NCOL + i];
    float d  = fabsf(vf - vr);
    double a = (double)d;
    double r = (double)(d / (fabsf(vr) + 1e-8f));

    #pragma unroll
    for (int off = 16; off > 0; off >>= 1) {
        a += __shfl_down_sync(0xffffffffu, a, off);
        r += __shfl_down_sync(0xffffffffu, r, off);
    }
    __shared__ double sa[32], sr[32];
    if (lane == 0) { sa[wid] = a; sr[wid] = r; }
    __syncthreads();
    if (tid == 0) {
        #pragma unroll
        for (int j = 1; j < 32; j++) { sa[0] += sa[j]; sr[0] += sr[j]; }
        g_pa[blockIdx.x] = sa[0];
        g_pr[blockIdx.x] = sr[0];
        __threadfence();
        unsigned prev = atomicAdd(&g_done2, 1u);
        if (prev == 15u) {                 // last block finalizes, fixed order
            __threadfence();
            double ta = 0.0, tr = 0.0;
            #pragma unroll
            for (int j = 0; j < 16; j++) { ta += g_pa[j]; tr += g_pr[j]; }
            out[0] = (float)(ta / (double)NCOL);
            out[1] = (float)(tr / (double)NCOL);
            g_done2 = 0;   // reset for next graph replay
        }
    }
}

extern "C" void kernel_launch(void* const* d_in, const int* in_sizes, int n_in,
                              void* d_out, int out_size) {
    const float* xf = (const float*)d_in[0];
    const float* xr = (const float*)d_in[1];
    const int smem_bytes = DEPTH * 256 * 16 + (G * CAPC + G) * 4 + NWARP * 256 * 2; // 43072
    cudaFuncSetAttribute(select_kernel,
                         cudaFuncAttributeMaxDynamicSharedMemorySize, smem_bytes);
    select_kernel<<<NBLOCKS, NTHREADS, smem_bytes>>>(xf, xr);

    cudaLaunchConfig_t cfg = {};
    cfg.gridDim = dim3(16, 1, 1);
    cfg.blockDim = dim3(1024, 1, 1);
    cfg.dynamicSmemBytes = 0;
    cfg.stream = 0;
    cudaLaunchAttribute attrs[1];
    attrs[0].id = cudaLaunchAttributeProgrammaticStreamSerialization;
    attrs[0].val.programmaticStreamSerializationAllowed = 1;
    cfg.attrs = attrs;
    cfg.numAttrs = 1;
    float* outp = (float*)d_out;
    cudaLaunchKernelEx(&cfg, reduce_kernel, outp);
}